// round 6
// baseline (speedup 1.0000x reference)
#include <cuda_runtime.h>
#include <cuda_bf16.h>
#include <cstdint>

#define CC 512
#define TT 8192
#define T_TILE 32
#define NTILES 4096              // 16 rows * 256 tiles
#define NTHREADS 512
#define GRID_P 148
#define DIVC 512.0f
#define EPSV 1e-8f
#define FULL 0xffffffffu
#define SLOT_F (CC * T_TILE)     // 16384 floats = 64KB per slot

// look-back records: {s_tot, q_tot, flag, pad}; flag 0=empty,1=aggregate,2=prefix
__device__ float4 g_rec[NTILES];

__global__ void init_rec_kernel() {
    int i = blockIdx.x * blockDim.x + threadIdx.x;
    if (i < NTILES) g_rec[i] = make_float4(0.f, 0.f, 0.f, 0.f);
}

__device__ __forceinline__ float4 ld_rec_vol(const float4* p) {
    float4 r;
    asm volatile("ld.volatile.global.v4.f32 {%0,%1,%2,%3}, [%4];"
                 : "=f"(r.x), "=f"(r.y), "=f"(r.z), "=f"(r.w) : "l"(p));
    return r;
}
__device__ __forceinline__ void st_rec_vol(float4* p, float s, float q, int flag) {
    asm volatile("st.volatile.global.v4.f32 [%0], {%1,%2,%3,%4};"
                 :: "l"(p), "f"(s), "f"(q), "f"(__int_as_float(flag)), "f"(0.f)
                 : "memory");
}

__device__ __forceinline__ void cp16(unsigned int sa, const float* gp) {
    asm volatile("cp.async.cg.shared.global [%0], [%1], 16;" :: "r"(sa), "l"(gp));
}
__device__ __forceinline__ void cp_commit() {
    asm volatile("cp.async.commit_group;" ::: "memory");
}
__device__ __forceinline__ void cp_wait1() {
    asm volatile("cp.async.wait_group 1;" ::: "memory");
}

__global__ void __launch_bounds__(NTHREADS, 1)
newNormal_kernel(const float* __restrict__ x,
                 const float* __restrict__ gains,
                 const float* __restrict__ bias,
                 float* __restrict__ out) {
    extern __shared__ float xs[];                 // 3 slots of [CC][T_TILE]
    __shared__ float4 parts_s[15][8];
    __shared__ float4 parts_q[15][8];
    __shared__ float4 mi4[2][16];                 // [parity][0..7]=mean4, [8..15]=inv4

    const int tid  = threadIdx.x;
    const int lane = tid & 31;
    const int w    = tid >> 5;                    // warp 15 = scanner
    const int r    = lane >> 3;                   // 0..3
    const int q    = lane & 7;                    // t-quarter (4t)
    const int cw   = 32 * w + r;                  // base channel of this lane's slice
    const int c0   = tid >> 3;                    // cp.async channel base (0..63)
    const int q8   = tid & 7;                     // cp.async 16B column

    const unsigned int sbase = (unsigned int)__cvta_generic_to_shared(xs);
    const int bid = blockIdx.x;

    // fixed per-thread gains/bias (channels cw + 4*k2)
    float gn[8], bsv[8];
#pragma unroll
    for (int k2 = 0; k2 < 8; k2++) {
        gn[k2]  = __ldg(gains + cw + 4 * k2);
        bsv[k2] = __ldg(bias  + cw + 4 * k2);
    }

    // issue one tile's cp.async group into a slot (always commits)
    auto issue = [&](int gt, int slot) {
        if (gt < NTILES) {
            const int b = gt >> 8, tc = gt & 255;
            const float* gp = x + ((size_t)(b * CC + c0)) * TT + tc * T_TILE + 4 * q8;
            unsigned int sa = sbase + (unsigned int)(slot * SLOT_F + c0 * T_TILE + 4 * q8) * 4u;
#pragma unroll
            for (int kk = 0; kk < 8; kk++)
                cp16(sa + (unsigned int)(64 * kk * T_TILE) * 4u, gp + (size_t)(64 * kk) * TT);
        }
        cp_commit();
    };

    // prologue: stage first two tiles
    issue(bid,          0);
    issue(bid + GRID_P, 1);
    cp_wait1();            // tile0 arrived
    __syncthreads();

    int k = 0;
    int g = bid;
    for (; g < NTILES; g += GRID_P, ++k) {
        const int tc = g & 255;
        const int t0 = tc * T_TILE;
        const float* sc = xs + (k % 3) * SLOT_F;

        // ---- partials of tile g from smem ----
        float4 s4 = make_float4(0.f,0.f,0.f,0.f), q4 = make_float4(0.f,0.f,0.f,0.f);
#pragma unroll
        for (int k2 = 0; k2 < 8; k2++) {
            float4 v = *(const float4*)(sc + (cw + 4 * k2) * T_TILE + 4 * q);
            s4.x += v.x; s4.y += v.y; s4.z += v.z; s4.w += v.w;
            q4.x = fmaf(v.x, v.x, q4.x); q4.y = fmaf(v.y, v.y, q4.y);
            q4.z = fmaf(v.z, v.z, q4.z); q4.w = fmaf(v.w, v.w, q4.w);
        }
#pragma unroll
        for (int d = 16; d >= 8; d >>= 1) {
            s4.x += __shfl_down_sync(FULL, s4.x, d); s4.y += __shfl_down_sync(FULL, s4.y, d);
            s4.z += __shfl_down_sync(FULL, s4.z, d); s4.w += __shfl_down_sync(FULL, s4.w, d);
            q4.x += __shfl_down_sync(FULL, q4.x, d); q4.y += __shfl_down_sync(FULL, q4.y, d);
            q4.z += __shfl_down_sync(FULL, q4.z, d); q4.w += __shfl_down_sync(FULL, q4.w, d);
        }

        if (w < 15) {
            if (lane < 8) { parts_s[w][lane] = s4; parts_q[w][lane] = q4; }
            asm volatile("bar.arrive 1, 512;" ::: "memory");
            // fall through to normalize prev — no wait on the scanner
        } else {
            asm volatile("bar.sync 1, 512;" ::: "memory");
            if (lane < 8) {
#pragma unroll
                for (int w2 = 0; w2 < 15; w2++) {
                    float4 a = parts_s[w2][lane];
                    s4.x += a.x; s4.y += a.y; s4.z += a.z; s4.w += a.w;
                    float4 c = parts_q[w2][lane];
                    q4.x += c.x; q4.y += c.y; q4.z += c.z; q4.w += c.w;
                }
            }
            // in-register inclusive scan within the 4-t group
            float4 is, iq;
            is.x = s4.x; is.y = is.x + s4.y; is.z = is.y + s4.z; is.w = is.z + s4.w;
            iq.x = q4.x; iq.y = iq.x + q4.y; iq.z = iq.y + q4.z; iq.w = iq.z + q4.w;
            // scan group totals across lanes 0..7
            float gs = is.w, gq = iq.w;
            float ssc = gs, qsc = gq;
#pragma unroll
            for (int d = 1; d < 8; d <<= 1) {
                float a = __shfl_up_sync(FULL, ssc, d, 8);
                float c = __shfl_up_sync(FULL, qsc, d, 8);
                if ((lane & 7) >= d && lane < 8) { ssc += a; qsc += c; }
            }
            const float exg_s = ssc - gs, exg_q = qsc - gq;
            const float tot_s = __shfl_sync(FULL, ssc, 7);
            const float tot_q = __shfl_sync(FULL, qsc, 7);

            // ---- decoupled look-back (warp-parallel, 32 records/round) ----
            float ex_s = 0.f, ex_q = 0.f;
            if (tc == 0) {
                if (lane == 0) st_rec_vol(&g_rec[g], tot_s, tot_q, 2);
            } else {
                if (lane == 0) st_rec_vol(&g_rec[g], tot_s, tot_q, 1);
                const int base = g & ~255;
                int p_hi = g - 1;
                for (;;) {
                    const int p = p_hi - lane;
                    float rs, rq; int f;
                    if (p >= base) {
                        float4 rr = ld_rec_vol(&g_rec[p]);
                        rs = rr.x; rq = rr.y; f = __float_as_int(rr.z);
                    } else { rs = 0.f; rq = 0.f; f = 2; }
                    if (__ballot_sync(FULL, f == 0)) { __nanosleep(32); continue; }
                    const unsigned m2 = __ballot_sync(FULL, f == 2);
                    float cs, cq;
                    if (m2) {
                        const int l2 = __ffs(m2) - 1;
                        cs = (lane <= l2) ? rs : 0.f;
                        cq = (lane <= l2) ? rq : 0.f;
                    } else { cs = rs; cq = rq; }
#pragma unroll
                    for (int d = 16; d; d >>= 1) {
                        cs += __shfl_down_sync(FULL, cs, d);
                        cq += __shfl_down_sync(FULL, cq, d);
                    }
                    ex_s += __shfl_sync(FULL, cs, 0);
                    ex_q += __shfl_sync(FULL, cq, 0);
                    if (m2) break;
                    p_hi -= 32;
                }
                if (lane == 0) st_rec_vol(&g_rec[g], ex_s + tot_s, ex_q + tot_q, 2);
            }

            // ---- mean / inv for this tile -> smem (consumed next iteration) ----
            if (lane < 8) {
                const float bsum = ex_s + exg_s;
                const float bq   = ex_q + exg_q;
                const int tg4 = t0 + 4 * lane;
                float4 m4, i4;
                {
                    float dv = 1.0f / ((float)(tg4 + 1) * DIVC);
                    float m = (bsum + is.x) * dv;
                    float var = fmaf(-m, m, (bq + iq.x) * dv);
                    m4.x = m; i4.x = rsqrtf(var + EPSV);
                }
                {
                    float dv = 1.0f / ((float)(tg4 + 2) * DIVC);
                    float m = (bsum + is.y) * dv;
                    float var = fmaf(-m, m, (bq + iq.y) * dv);
                    m4.y = m; i4.y = rsqrtf(var + EPSV);
                }
                {
                    float dv = 1.0f / ((float)(tg4 + 3) * DIVC);
                    float m = (bsum + is.z) * dv;
                    float var = fmaf(-m, m, (bq + iq.z) * dv);
                    m4.z = m; i4.z = rsqrtf(var + EPSV);
                }
                {
                    float dv = 1.0f / ((float)(tg4 + 4) * DIVC);
                    float m = (bsum + is.w) * dv;
                    float var = fmaf(-m, m, (bq + iq.w) * dv);
                    m4.w = m; i4.w = rsqrtf(var + EPSV);
                }
                mi4[k & 1][lane]     = m4;
                mi4[k & 1][8 + lane] = i4;
            }
        }

        // ---- normalize + store tile g-GRID_P (overlaps scanner look-back) ----
        if (k > 0) {
            const int gp_id = g - GRID_P;
            const int bp  = gp_id >> 8;
            const int t0p = (gp_id & 255) * T_TILE;
            const float* sp = xs + ((k - 1) % 3) * SLOT_F;
            const float4 m4 = mi4[(k - 1) & 1][q];
            const float4 i4 = mi4[(k - 1) & 1][8 + q];
            float* op = out + ((size_t)(bp * CC + cw)) * TT + t0p + 4 * q;
#pragma unroll
            for (int k2 = 0; k2 < 8; k2++) {
                float4 v = *(const float4*)(sp + (cw + 4 * k2) * T_TILE + 4 * q);
                float4 o;
                o.x = fmaf((v.x - m4.x) * i4.x, gn[k2], bsv[k2]);
                o.y = fmaf((v.y - m4.y) * i4.y, gn[k2], bsv[k2]);
                o.z = fmaf((v.z - m4.z) * i4.z, gn[k2], bsv[k2]);
                o.w = fmaf((v.w - m4.w) * i4.w, gn[k2], bsv[k2]);
                __stcs((float4*)(op + (size_t)(4 * k2) * TT), o);
            }
        }

        __syncthreads();                       // slot (k-1)%3 free; mi[k&1] published
        issue(g + 2 * GRID_P, (k + 2) % 3);    // overwrites slot (k-1)%3 — safe now
        cp_wait1();                            // tile g+GRID_P complete
        __syncthreads();                       // cross-thread smem visibility
    }

    // ---- epilogue: normalize the final tile ----
    if (k > 0) {
        const int gp_id = g - GRID_P;
        const int bp  = gp_id >> 8;
        const int t0p = (gp_id & 255) * T_TILE;
        const float* sp = xs + ((k - 1) % 3) * SLOT_F;
        const float4 m4 = mi4[(k - 1) & 1][q];
        const float4 i4 = mi4[(k - 1) & 1][8 + q];
        float* op = out + ((size_t)(bp * CC + cw)) * TT + t0p + 4 * q;
#pragma unroll
        for (int k2 = 0; k2 < 8; k2++) {
            float4 v = *(const float4*)(sp + (cw + 4 * k2) * T_TILE + 4 * q);
            float4 o;
            o.x = fmaf((v.x - m4.x) * i4.x, gn[k2], bsv[k2]);
            o.y = fmaf((v.y - m4.y) * i4.y, gn[k2], bsv[k2]);
            o.z = fmaf((v.z - m4.z) * i4.z, gn[k2], bsv[k2]);
            o.w = fmaf((v.w - m4.w) * i4.w, gn[k2], bsv[k2]);
            __stcs((float4*)(op + (size_t)(4 * k2) * TT), o);
        }
    }
}

extern "C" void kernel_launch(void* const* d_in, const int* in_sizes, int n_in,
                              void* d_out, int out_size) {
    (void)in_sizes; (void)n_in; (void)out_size;
    const float* x     = (const float*)d_in[0];
    const float* gains = (const float*)d_in[1];
    const float* bias  = (const float*)d_in[2];
    float* out = (float*)d_out;

    const int smem_bytes = 3 * SLOT_F * sizeof(float);   // 196608
    static int attr_set = 0;
    if (!attr_set) {
        cudaFuncSetAttribute(newNormal_kernel,
                             cudaFuncAttributeMaxDynamicSharedMemorySize, smem_bytes);
        attr_set = 1;
    }

    init_rec_kernel<<<(NTILES + 255) / 256, 256>>>();
    newNormal_kernel<<<GRID_P, NTHREADS, smem_bytes>>>(x, gains, bias, out);
}

// round 7
// speedup vs baseline: 1.0773x; 1.0773x over previous
#include <cuda_runtime.h>
#include <cuda_bf16.h>
#include <cstdint>

#define BB 16
#define CC 512
#define TT 8192
#define T_TILE 16
#define TPB (TT / T_TILE)        // 512 tiles per batch row
#define NTILES (BB * TPB)        // 8192
#define NTHREADS 256
#define GRID_P 296               // 2 CTAs per SM
#define DIVC 512.0f
#define EPSV 1e-8f
#define FULL 0xffffffffu

// one 16B record per tile: {s, q, flag, pad}; flag: 0=empty, 1=agg, 2=inclusive prefix
__device__ float4 g_rec[NTILES];

__global__ void init_rec_kernel() {
    int i = blockIdx.x * blockDim.x + threadIdx.x;
    if (i < NTILES) g_rec[i] = make_float4(0.f, 0.f, 0.f, 0.f);
}

__device__ __forceinline__ float4 ld_rec_vol(const float4* p) {
    float4 r;
    asm volatile("ld.volatile.global.v4.f32 {%0,%1,%2,%3}, [%4];"
                 : "=f"(r.x), "=f"(r.y), "=f"(r.z), "=f"(r.w) : "l"(p));
    return r;
}
__device__ __forceinline__ void st_rec_vol(float4* p, float s, float q, int flag) {
    asm volatile("st.volatile.global.v4.f32 [%0], {%1,%2,%3,%4};"
                 :: "l"(p), "f"(s), "f"(q), "f"(__int_as_float(flag)), "f"(0.f)
                 : "memory");
}

__global__ void __launch_bounds__(NTHREADS, 2)
newNormal_kernel(const float* __restrict__ x,
                 const float* __restrict__ gains,
                 const float* __restrict__ bias,
                 float* __restrict__ out) {
    __shared__ float4 parts_s[8][4];
    __shared__ float4 parts_q[8][4];
    __shared__ float meanv[T_TILE], invv[T_TILE];

    const int tid  = threadIdx.x;
    const int tg4  = tid & 3;      // t-quarter: t = 4*tg4 .. 4*tg4+3
    const int j    = tid >> 2;     // 0..63 ; channels c = j + 64*k, k=0..7
    const int lane = tid & 31;
    const int w    = tid >> 5;     // 0..7 ; warp 7 = scanner

    // fixed per-thread gains/bias
    float gn[8], bsv[8];
#pragma unroll
    for (int k = 0; k < 8; k++) {
        gn[k]  = __ldg(gains + j + 64 * k);
        bsv[k] = __ldg(bias  + j + 64 * k);
    }

    float4 cur[8], nxt[8];

    int g = blockIdx.x;
    if (g < NTILES) {
        const int b = g >> 9, tc = g & 511;
        const float* p = x + ((size_t)(b * CC + j)) * TT + tc * T_TILE + 4 * tg4;
#pragma unroll
        for (int k = 0; k < 8; k++)
            cur[k] = __ldg((const float4*)(p + (size_t)(64 * k) * TT));
    }

    for (; g < NTILES; g += GRID_P) {
        const int b  = g >> 9;
        const int tc = g & 511;
        const int t0 = tc * T_TILE;
        const int gnx = g + GRID_P;

        // ---- prefetch next tile (latency hidden behind this iteration) ----
        if (gnx < NTILES) {
            const int b2 = gnx >> 9, tc2 = gnx & 511;
            const float* p = x + ((size_t)(b2 * CC + j)) * TT + tc2 * T_TILE + 4 * tg4;
#pragma unroll
            for (int k = 0; k < 8; k++)
                nxt[k] = __ldg((const float4*)(p + (size_t)(64 * k) * TT));
        }

        // ---- per-thread partials over 8 channels for its 4 t ----
        float4 s4 = make_float4(0.f,0.f,0.f,0.f), q4 = make_float4(0.f,0.f,0.f,0.f);
#pragma unroll
        for (int k = 0; k < 8; k++) {
            float4 v = cur[k];
            s4.x += v.x; s4.y += v.y; s4.z += v.z; s4.w += v.w;
            q4.x = fmaf(v.x, v.x, q4.x); q4.y = fmaf(v.y, v.y, q4.y);
            q4.z = fmaf(v.z, v.z, q4.z); q4.w = fmaf(v.w, v.w, q4.w);
        }
        // reduce over the 8 j-values in this warp (lanes tg4, tg4+4, ..., tg4+28)
#pragma unroll
        for (int d = 16; d >= 4; d >>= 1) {
            s4.x += __shfl_down_sync(FULL, s4.x, d); s4.y += __shfl_down_sync(FULL, s4.y, d);
            s4.z += __shfl_down_sync(FULL, s4.z, d); s4.w += __shfl_down_sync(FULL, s4.w, d);
            q4.x += __shfl_down_sync(FULL, q4.x, d); q4.y += __shfl_down_sync(FULL, q4.y, d);
            q4.z += __shfl_down_sync(FULL, q4.z, d); q4.w += __shfl_down_sync(FULL, q4.w, d);
        }
        if (lane < 4) { parts_s[w][lane] = s4; parts_q[w][lane] = q4; }
        __syncthreads();

        // ---- scanner warp: combine, scan, look-back, mean/inv ----
        if (w == 7) {
            float4 S = make_float4(0.f,0.f,0.f,0.f), Q = make_float4(0.f,0.f,0.f,0.f);
            if (lane < 4) {
#pragma unroll
                for (int w2 = 0; w2 < 8; w2++) {
                    float4 a = parts_s[w2][lane];
                    S.x += a.x; S.y += a.y; S.z += a.z; S.w += a.w;
                    float4 c = parts_q[w2][lane];
                    Q.x += c.x; Q.y += c.y; Q.z += c.z; Q.w += c.w;
                }
            }
            // in-register inclusive scan within the 4-t group
            float4 is, iq;
            is.x = S.x; is.y = is.x + S.y; is.z = is.y + S.z; is.w = is.z + S.w;
            iq.x = Q.x; iq.y = iq.x + Q.y; iq.z = iq.y + Q.z; iq.w = iq.z + Q.w;
            // scan group totals across lanes 0..3
            float gs = is.w, gq = iq.w;
            float ssc = gs, qsc = gq;
#pragma unroll
            for (int d = 1; d < 4; d <<= 1) {
                float a = __shfl_up_sync(FULL, ssc, d, 4);
                float c = __shfl_up_sync(FULL, qsc, d, 4);
                if ((lane & 3) >= d && lane < 4) { ssc += a; qsc += c; }
            }
            const float exg_s = ssc - gs, exg_q = qsc - gq;
            const float tot_s = __shfl_sync(FULL, ssc, 3);
            const float tot_q = __shfl_sync(FULL, qsc, 3);

            // decoupled look-back (warp-parallel, 32 records/round)
            float ex_s = 0.f, ex_q = 0.f;
            if (tc == 0) {
                if (lane == 0) st_rec_vol(&g_rec[g], tot_s, tot_q, 2);
            } else {
                if (lane == 0) st_rec_vol(&g_rec[g], tot_s, tot_q, 1);
                const int base = g & ~511;
                int p_hi = g - 1;
                for (;;) {
                    const int p = p_hi - lane;
                    float rs, rq; int f;
                    if (p >= base) {
                        float4 rr = ld_rec_vol(&g_rec[p]);
                        rs = rr.x; rq = rr.y; f = __float_as_int(rr.z);
                    } else { rs = 0.f; rq = 0.f; f = 2; }
                    if (__ballot_sync(FULL, f == 0)) { __nanosleep(32); continue; }
                    const unsigned m2 = __ballot_sync(FULL, f == 2);
                    float cs, cq;
                    if (m2) {
                        const int l2 = __ffs(m2) - 1;
                        cs = (lane <= l2) ? rs : 0.f;
                        cq = (lane <= l2) ? rq : 0.f;
                    } else { cs = rs; cq = rq; }
#pragma unroll
                    for (int d = 16; d; d >>= 1) {
                        cs += __shfl_down_sync(FULL, cs, d);
                        cq += __shfl_down_sync(FULL, cq, d);
                    }
                    ex_s += __shfl_sync(FULL, cs, 0);
                    ex_q += __shfl_sync(FULL, cq, 0);
                    if (m2) break;
                    p_hi -= 32;
                }
                if (lane == 0) st_rec_vol(&g_rec[g], ex_s + tot_s, ex_q + tot_q, 2);
            }

            // mean / rsqrt (lanes 0..3, one float4 of t each)
            if (lane < 4) {
                const float bs = ex_s + exg_s;
                const float bq = ex_q + exg_q;
                const int tb = t0 + 4 * lane;
                float4 m4, i4;
                {
                    float dv = 1.0f / ((float)(tb + 1) * DIVC);
                    float m = (bs + is.x) * dv;
                    float var = fmaf(-m, m, (bq + iq.x) * dv);
                    m4.x = m; i4.x = rsqrtf(var + EPSV);
                }
                {
                    float dv = 1.0f / ((float)(tb + 2) * DIVC);
                    float m = (bs + is.y) * dv;
                    float var = fmaf(-m, m, (bq + iq.y) * dv);
                    m4.y = m; i4.y = rsqrtf(var + EPSV);
                }
                {
                    float dv = 1.0f / ((float)(tb + 3) * DIVC);
                    float m = (bs + is.z) * dv;
                    float var = fmaf(-m, m, (bq + iq.z) * dv);
                    m4.z = m; i4.z = rsqrtf(var + EPSV);
                }
                {
                    float dv = 1.0f / ((float)(tb + 4) * DIVC);
                    float m = (bs + is.w) * dv;
                    float var = fmaf(-m, m, (bq + iq.w) * dv);
                    m4.w = m; i4.w = rsqrtf(var + EPSV);
                }
                *(float4*)&meanv[4 * lane] = m4;
                *(float4*)&invv[4 * lane]  = i4;
            }
        }
        __syncthreads();

        // ---- normalize + store ----
        {
            const float4 m4 = *(const float4*)&meanv[4 * tg4];
            const float4 i4 = *(const float4*)&invv[4 * tg4];
            float* po = out + ((size_t)(b * CC + j)) * TT + t0 + 4 * tg4;
#pragma unroll
            for (int k = 0; k < 8; k++) {
                float4 v = cur[k];
                float4 o;
                o.x = fmaf((v.x - m4.x) * i4.x, gn[k], bsv[k]);
                o.y = fmaf((v.y - m4.y) * i4.y, gn[k], bsv[k]);
                o.z = fmaf((v.z - m4.z) * i4.z, gn[k], bsv[k]);
                o.w = fmaf((v.w - m4.w) * i4.w, gn[k], bsv[k]);
                __stcs((float4*)(po + (size_t)(64 * k) * TT), o);
            }
        }

#pragma unroll
        for (int k = 0; k < 8; k++) cur[k] = nxt[k];
        __syncthreads();   // meanv/invv consumed before next iteration overwrites
    }
}

extern "C" void kernel_launch(void* const* d_in, const int* in_sizes, int n_in,
                              void* d_out, int out_size) {
    (void)in_sizes; (void)n_in; (void)out_size;
    const float* x     = (const float*)d_in[0];
    const float* gains = (const float*)d_in[1];
    const float* bias  = (const float*)d_in[2];
    float* out = (float*)d_out;

    init_rec_kernel<<<(NTILES + 255) / 256, 256>>>();
    newNormal_kernel<<<GRID_P, NTHREADS>>>(x, gains, bias, out);
}